// round 4
// baseline (speedup 1.0000x reference)
#include <cuda_runtime.h>
#include <math_constants.h>

#define N_TOK   262144
#define K_CODES 1024
#define D_DIM   64
#define HW      4096
#define CHW     262144
#define Q_ELEMS 16777216

// ---------------- scratch (device globals; no allocation allowed) ----------------
__device__ float g_Wt[D_DIM * K_CODES];     // transposed weight [d][k]
__device__ float g_wnh[K_CODES];            // 0.5*||w_k||^2
__device__ float g_counts[K_CODES];
__device__ float g_dw[K_CODES * D_DIM];
__device__ float g_neww[K_CODES * D_DIM];
__device__ float g_loss;
__device__ int   g_idx[N_TOK];
__device__ int2  g_top2[N_TOK];             // fp32-pass top-2 candidate codes

// tie-aware "less" : smaller score wins; equal score -> lower index wins
__device__ __forceinline__ bool lt2(float s, int k, float s2, int k2) {
    return (s < s2) || (s == s2 && k < k2);
}

// ---------------- kernel 1: zero accumulators (graph-replay safe) ----------------
__global__ void k_zero() {
    int i = blockIdx.x * blockDim.x + threadIdx.x;
    if (i < K_CODES) g_counts[i] = 0.f;
    if (i < K_CODES * D_DIM) g_dw[i] = 0.f;
    if (i == 0) g_loss = 0.f;
}

// ---------------- kernel 2: transpose weight + half-norms ----------------
__global__ void k_prep(const float* __restrict__ w) {
    int k = blockIdx.x * 256 + threadIdx.x;   // 0..1023
    float ss = 0.f;
#pragma unroll
    for (int d = 0; d < 64; d++) {
        float v = w[k * 64 + d];
        g_Wt[d * 1024 + k] = v;               // coalesced writes (lanes vary k)
        ss = fmaf(v, v, ss);
    }
    g_wnh[k] = 0.5f * ss;
}

// ---------------- kernel 3: fp32 distances -> top-2 candidates per token ----------
// Block: 128 tokens x full K (8 tiles of 128 codes). 256 threads, 8x8 micro-tile.
__global__ __launch_bounds__(256, 2)
void k_argmin(const float* __restrict__ in) {
    extern __shared__ float smem[];
    float* A_s  = smem;                      // [64][128] d-major
    float* W_s  = smem + 64 * 128;           // [64][128] d-major
    float* wn_s = smem + 2 * 64 * 128;       // [128]

    const int tid = threadIdx.x;
    const int ty  = tid >> 4;                // 0..15 : token group (8 tokens)
    const int tx  = tid & 15;                // 0..15 : code group  (8 codes)
    const int token0 = blockIdx.x * 128;
    const int b   = token0 >> 12;
    const int hw0 = token0 & 4095;
    const float* Abase = in + (size_t)b * CHW + hw0;

    // Load A tile [64 d][128 tok] — NCHW layout is already d-major: coalesced.
#pragma unroll
    for (int r = 0; r < 8; r++) {
        int m = r * 256 + tid;               // 0..2047 float4 slots
        int d = m >> 5;
        int c = (m & 31) * 4;
        *(float4*)(A_s + d * 128 + c) = *(const float4*)(Abase + d * HW + c);
    }

    float rb1[8], rb2[8];
    int   ri1[8], ri2[8];
#pragma unroll
    for (int i = 0; i < 8; i++) {
        rb1[i] = CUDART_INF_F; rb2[i] = CUDART_INF_F; ri1[i] = 0; ri2[i] = 0;
    }

    for (int kt = 0; kt < 8; kt++) {
        const int k0 = kt * 128;
        __syncthreads();                     // protect W_s from previous tile readers
#pragma unroll
        for (int r = 0; r < 8; r++) {
            int m = r * 256 + tid;
            int d = m >> 5;
            int c = (m & 31) * 4;
            *(float4*)(W_s + d * 128 + c) = *(const float4*)(g_Wt + d * 1024 + k0 + c);
        }
        if (tid < 32) ((float4*)wn_s)[tid] = ((const float4*)(g_wnh + k0))[tid];
        __syncthreads();

        float acc[8][8];
#pragma unroll
        for (int i = 0; i < 8; i++)
#pragma unroll
            for (int j = 0; j < 8; j++) acc[i][j] = 0.f;

#pragma unroll 4
        for (int d = 0; d < 64; d++) {
            float4 a0 = *(const float4*)(A_s + d * 128 + ty * 8);
            float4 a1 = *(const float4*)(A_s + d * 128 + ty * 8 + 4);
            float4 b0 = *(const float4*)(W_s + d * 128 + tx * 8);
            float4 b1 = *(const float4*)(W_s + d * 128 + tx * 8 + 4);
            float av[8] = {a0.x, a0.y, a0.z, a0.w, a1.x, a1.y, a1.z, a1.w};
            float bv[8] = {b0.x, b0.y, b0.z, b0.w, b1.x, b1.y, b1.z, b1.w};
#pragma unroll
            for (int i = 0; i < 8; i++)
#pragma unroll
                for (int j = 0; j < 8; j++)
                    acc[i][j] = fmaf(av[i], bv[j], acc[i][j]);
        }

        // top-2 epilogue: score = 0.5||w||^2 - x.w  (monotone in distance)
#pragma unroll
        for (int i = 0; i < 8; i++) {
            float b1 = CUDART_INF_F, b2 = CUDART_INF_F;
            int   i1 = 0, i2 = 0;
#pragma unroll
            for (int j = 0; j < 8; j++) {
                float s = wn_s[tx * 8 + j] - acc[i][j];
                int   k = k0 + tx * 8 + j;
                if (lt2(s, k, b1, i1)) { b2 = b1; i2 = i1; b1 = s; i1 = k; }
                else if (lt2(s, k, b2, i2)) { b2 = s; i2 = k; }
            }
            // merge sorted pairs across 16 tx lanes (butterfly)
#pragma unroll
            for (int off = 1; off < 16; off <<= 1) {
                float c1 = __shfl_xor_sync(0xffffffffu, b1, off, 16);
                int   j1 = __shfl_xor_sync(0xffffffffu, i1, off, 16);
                float c2 = __shfl_xor_sync(0xffffffffu, b2, off, 16);
                int   j2 = __shfl_xor_sync(0xffffffffu, i2, off, 16);
                if (lt2(c1, j1, b1, i1)) {
                    float tb = b1; int tk = i1;
                    b1 = c1; i1 = j1;
                    if (lt2(c2, j2, tb, tk)) { b2 = c2; i2 = j2; }
                    else                      { b2 = tb; i2 = tk; }
                } else {
                    if (lt2(c1, j1, b2, i2)) { b2 = c1; i2 = j1; }
                }
            }
            // merge tile result into running top-2
            if (lt2(b1, i1, rb1[i], ri1[i])) {
                float tb = rb1[i]; int tk = ri1[i];
                rb1[i] = b1; ri1[i] = i1;
                if (lt2(b2, i2, tb, tk)) { rb2[i] = b2; ri2[i] = i2; }
                else                      { rb2[i] = tb; ri2[i] = tk; }
            } else if (lt2(b1, i1, rb2[i], ri2[i])) {
                rb2[i] = b1; ri2[i] = i1;
            }
        }
    }

    if (tx == 0) {
#pragma unroll
        for (int i = 0; i < 8; i++)
            g_top2[token0 + ty * 8 + i] = make_int2(ri1[i], ri2[i]);
    }
}

// ---------------- kernel 3b: fp64 exact repair + scatters ----------------
__global__ __launch_bounds__(256)
void k_fix(const float* __restrict__ in, const float* __restrict__ w,
           float* __restrict__ out_idx_f) {
    const int t  = blockIdx.x * 256 + threadIdx.x;
    const int b  = t >> 12;
    const int hw = t & 4095;
    const int2 c = g_top2[t];
    const float* x = in + (size_t)b * CHW + hw;
    const float4* w1 = (const float4*)(w + c.x * 64);
    const float4* w2 = (const float4*)(w + c.y * 64);

    double d1 = 0.0, d2 = 0.0;
#pragma unroll
    for (int q = 0; q < 16; q++) {
        float4 w1v = w1[q];
        float4 w2v = w2[q];
#pragma unroll
        for (int r = 0; r < 4; r++) {
            double xv = (double)x[(size_t)(q * 4 + r) * HW];
            double e1 = xv - (double)((&w1v.x)[r]);
            double e2 = xv - (double)((&w2v.x)[r]);
            d1 = fma(e1, e1, d1);
            d2 = fma(e2, e2, d2);
        }
    }
    int k = (d2 < d1 || (d2 == d1 && c.y < c.x)) ? c.y : c.x;
    g_idx[t]     = k;
    out_idx_f[t] = (float)k;
    atomicAdd(&g_counts[k], 1.0f);
    float* dwrow = g_dw + k * 64;
#pragma unroll 8
    for (int d = 0; d < 64; d++)
        atomicAdd(&dwrow[d], x[(size_t)d * HW]);   // L1 hits (just loaded above)
}

// ---------------- kernel 4: EMA update -> new codebook ----------------
__global__ void k_update(const float* __restrict__ ecs, const float* __restrict__ ew) {
    __shared__ float red[1024];
    int k = threadIdx.x;
    float cs = ecs[k] * 0.99f + 0.01f * g_counts[k];
    red[k] = cs;
    __syncthreads();
    for (int s = 512; s > 0; s >>= 1) {
        if (k < s) red[k] += red[k + s];
        __syncthreads();
    }
    float n = red[0];
    float csn = (cs + 1e-5f) / (n + 1024.0f * 1e-5f) * n;   // Laplace smoothing
#pragma unroll 8
    for (int d = 0; d < 64; d++) {
        float e = ew[k * 64 + d] * 0.99f + 0.01f * g_dw[k * 64 + d];
        g_neww[k * 64 + d] = e / csn;
    }
}

// ---------------- kernel 5: gather + straight-through + loss partials ----------------
__global__ __launch_bounds__(256)
void k_gather(const float* __restrict__ in, float* __restrict__ out_q) {
    __shared__ float q_s[128 * 68];          // padded rows (avoid worst bank conflicts)
    __shared__ int   idx_s[128];
    __shared__ float part[8];
    const int tid = threadIdx.x;
    const int token0 = blockIdx.x * 128;
    const int b   = token0 >> 12;
    const int hw0 = token0 & 4095;

    if (tid < 128) idx_s[tid] = g_idx[token0 + tid];
    __syncthreads();

    // stage 128 codebook rows into smem (coalesced float4 gathers from L2-resident table)
#pragma unroll
    for (int r = 0; r < 8; r++) {
        int m  = r * 256 + tid;              // 2048 float4
        int t  = m >> 4;
        int sg = (m & 15) * 4;
        float4 v = *(const float4*)(g_neww + idx_s[t] * 64 + sg);
        *(float4*)(q_s + t * 68 + sg) = v;
    }
    __syncthreads();

    const size_t base = (size_t)b * CHW + hw0;
    float lsum = 0.f;
#pragma unroll 4
    for (int it = 0; it < 32; it++) {
        int d = it * 2 + (tid >> 7);
        int t = tid & 127;
        size_t g = base + (size_t)d * HW + t;
        float x  = in[g];
        float q  = q_s[t * 68 + d];
        float dt = q - x;                    // matches reference rounding order
        out_q[g] = x + dt;                   // straight-through: x + (q - x)
        lsum = fmaf(dt, dt, lsum);
    }
#pragma unroll
    for (int off = 16; off > 0; off >>= 1)
        lsum += __shfl_xor_sync(0xffffffffu, lsum, off);
    if ((tid & 31) == 0) part[tid >> 5] = lsum;
    __syncthreads();
    if (tid == 0) {
        float s = 0.f;
#pragma unroll
        for (int i = 0; i < 8; i++) s += part[i];
        atomicAdd(&g_loss, s);
    }
}

// ---------------- kernel 6: finalize loss ----------------
__global__ void k_final(float* out) {
    out[0] = 0.25f * (g_loss * (1.0f / 16777216.0f));
}

// ---------------- launch ----------------
extern "C" void kernel_launch(void* const* d_in, const int* in_sizes, int n_in,
                              void* d_out, int out_size) {
    const float* in  = (const float*)d_in[0];   // (64,64,64,64) NCHW
    const float* w   = (const float*)d_in[1];   // (1024,64)
    const float* ecs = (const float*)d_in[2];   // (1024,)
    const float* ew  = (const float*)d_in[3];   // (1024,64)
    float* out      = (float*)d_out;            // [loss | quantized NCHW | idx]
    float* out_q    = out + 1;
    float* out_idx  = out + 1 + Q_ELEMS;

    const int ARG_SMEM = (2 * 64 * 128 + 128) * 4;  // 66048 B

    k_zero<<<(K_CODES * D_DIM + 255) / 256, 256>>>();
    k_prep<<<4, 256>>>(w);
    cudaFuncSetAttribute(k_argmin, cudaFuncAttributeMaxDynamicSharedMemorySize, ARG_SMEM);
    k_argmin<<<N_TOK / 128, 256, ARG_SMEM>>>(in);
    k_fix<<<N_TOK / 256, 256>>>(in, w, out_idx);
    k_update<<<1, 1024>>>(ecs, ew);
    k_gather<<<N_TOK / 128, 256>>>(in, out_q);
    k_final<<<1, 1>>>(out);
}